// round 1
// baseline (speedup 1.0000x reference)
#include <cuda_runtime.h>

constexpr int NN = 50000;
constexpr int NE = 800000;

// ---------------- scratch (no allocs allowed; __device__ globals) -----------
__device__ float g_mean[NN * 128];
__device__ float g_h1[NN * 128];
__device__ float g_h2[NN * 128];
__device__ float g_pre[NN * 64];
__device__ int   g_csr[NE];
__device__ int   g_cnt[NN];
__device__ int   g_off[NN + 1];
__device__ int   g_cur[NN];

// ---------------- CSR build -------------------------------------------------
__global__ void k_zero_cnt() {
    int i = blockIdx.x * blockDim.x + threadIdx.x;
    if (i < NN) g_cnt[i] = 0;
}

__global__ void k_count(const int* __restrict__ dst) {
    int i = blockIdx.x * blockDim.x + threadIdx.x;
    if (i < NE) atomicAdd(&g_cnt[dst[i]], 1);
}

__global__ void k_scan() {
    __shared__ int sh[1024];
    __shared__ int carry;
    if (threadIdx.x == 0) carry = 0;
    __syncthreads();
    for (int base = 0; base < NN; base += 1024) {
        int i = base + threadIdx.x;
        int v = (i < NN) ? g_cnt[i] : 0;
        sh[threadIdx.x] = v;
        __syncthreads();
        for (int s = 1; s < 1024; s <<= 1) {
            int t = (threadIdx.x >= s) ? sh[threadIdx.x - s] : 0;
            __syncthreads();
            sh[threadIdx.x] += t;
            __syncthreads();
        }
        int excl = sh[threadIdx.x] - v + carry;
        if (i < NN) { g_off[i] = excl; g_cur[i] = excl; }
        __syncthreads();
        if (threadIdx.x == 0) carry += sh[1023];
        __syncthreads();
    }
    if (threadIdx.x == 0) g_off[NN] = carry;
}

__global__ void k_scatter(const int* __restrict__ src, const int* __restrict__ dst) {
    int i = blockIdx.x * blockDim.x + threadIdx.x;
    if (i < NE) {
        int d = dst[i];
        int pos = atomicAdd(&g_cur[d], 1);
        g_csr[pos] = src[i];
    }
}

// ---------------- aggregation: one warp per node, float4 lanes --------------
__global__ void k_agg(const float* __restrict__ X, float* __restrict__ M) {
    int w = (blockIdx.x * blockDim.x + threadIdx.x) >> 5;
    int lane = threadIdx.x & 31;
    if (w >= NN) return;
    int s = g_off[w], e = g_off[w + 1];
    float4 a0 = {0.f, 0.f, 0.f, 0.f}, a1 = a0, a2 = a0, a3 = a0;
    int j = s;
    for (; j + 4 <= e; j += 4) {
        int i0 = g_csr[j], i1 = g_csr[j + 1], i2 = g_csr[j + 2], i3 = g_csr[j + 3];
        float4 v0 = *(const float4*)(X + (size_t)i0 * 128 + lane * 4);
        float4 v1 = *(const float4*)(X + (size_t)i1 * 128 + lane * 4);
        float4 v2 = *(const float4*)(X + (size_t)i2 * 128 + lane * 4);
        float4 v3 = *(const float4*)(X + (size_t)i3 * 128 + lane * 4);
        a0.x += v0.x; a0.y += v0.y; a0.z += v0.z; a0.w += v0.w;
        a1.x += v1.x; a1.y += v1.y; a1.z += v1.z; a1.w += v1.w;
        a2.x += v2.x; a2.y += v2.y; a2.z += v2.z; a2.w += v2.w;
        a3.x += v3.x; a3.y += v3.y; a3.z += v3.z; a3.w += v3.w;
    }
    for (; j < e; j++) {
        int i0 = g_csr[j];
        float4 v0 = *(const float4*)(X + (size_t)i0 * 128 + lane * 4);
        a0.x += v0.x; a0.y += v0.y; a0.z += v0.z; a0.w += v0.w;
    }
    a0.x += a1.x + a2.x + a3.x;
    a0.y += a1.y + a2.y + a3.y;
    a0.z += a1.z + a2.z + a3.z;
    a0.w += a1.w + a2.w + a3.w;
    int c = e - s; if (c < 1) c = 1;
    float inv = 1.0f / (float)c;
    float4 r; r.x = a0.x * inv; r.y = a0.y * inv; r.z = a0.z * inv; r.w = a0.w * inv;
    *(float4*)(M + (size_t)w * 128 + lane * 4) = r;
}

// ---------------- SAGE GEMM: C = relu(A1@W1 + A2@W2 + b), K=128 each --------
// Block: 128 rows x 128 cols, 256 threads, 8x8 microtile, weights resident in smem.
#define AS_STRIDE 132
#define SAGE_SMEM (256 * 128 * 4 + 2 * 8 * AS_STRIDE * 4)

__global__ __launch_bounds__(256) void k_sage(
    const float* __restrict__ A1, const float* __restrict__ A2,
    const float* __restrict__ W1, const float* __restrict__ W2,
    const float* __restrict__ bias, float* __restrict__ C)
{
    extern __shared__ float sm[];
    float* Ws = sm;                 // [256][128]
    float* As = sm + 256 * 128;     // [2][8][AS_STRIDE]
    int tid = threadIdx.x;

    for (int i = tid; i < 256 * 128 / 4; i += 256) {
        int k = (i * 4) >> 7;
        int jc = (i * 4) & 127;
        const float* p = (k < 128) ? (W1 + (size_t)k * 128 + jc)
                                   : (W2 + (size_t)(k - 128) * 128 + jc);
        ((float4*)Ws)[i] = *(const float4*)p;
    }

    int r0 = blockIdx.x * 128;
    int lrow = tid >> 1;
    int kpart = (tid & 1) * 4;
    int ty = tid >> 4, tx = tid & 15;

    float acc[8][8];
#pragma unroll
    for (int i = 0; i < 8; i++)
#pragma unroll
        for (int jj = 0; jj < 8; jj++) acc[i][jj] = 0.f;

    auto loadA = [&](int kc, int buf) {
        int kg = kc * 8 + kpart;
        const float* srcp = (kg < 128) ? A1 : A2;
        int kk = kg & 127;
        int gr = r0 + lrow;
        float4 v = {0.f, 0.f, 0.f, 0.f};
        if (gr < NN) v = *(const float4*)(srcp + (size_t)gr * 128 + kk);
        float* d2 = As + buf * 8 * AS_STRIDE;
        d2[(kpart + 0) * AS_STRIDE + lrow] = v.x;
        d2[(kpart + 1) * AS_STRIDE + lrow] = v.y;
        d2[(kpart + 2) * AS_STRIDE + lrow] = v.z;
        d2[(kpart + 3) * AS_STRIDE + lrow] = v.w;
    };

    loadA(0, 0);
    __syncthreads();
    for (int kc = 0; kc < 32; kc++) {
        if (kc + 1 < 32) loadA(kc + 1, (kc + 1) & 1);
        const float* Ab = As + (kc & 1) * 8 * AS_STRIDE;
#pragma unroll
        for (int kk = 0; kk < 8; kk++) {
            float a[8], w[8];
            *(float4*)(a)     = *(const float4*)(Ab + kk * AS_STRIDE + ty * 8);
            *(float4*)(a + 4) = *(const float4*)(Ab + kk * AS_STRIDE + ty * 8 + 4);
            const float* wr = Ws + (kc * 8 + kk) * 128 + tx * 8;
            *(float4*)(w)     = *(const float4*)(wr);
            *(float4*)(w + 4) = *(const float4*)(wr + 4);
#pragma unroll
            for (int i = 0; i < 8; i++)
#pragma unroll
                for (int jj = 0; jj < 8; jj++)
                    acc[i][jj] = fmaf(a[i], w[jj], acc[i][jj]);
        }
        __syncthreads();
    }

    float bv[8];
#pragma unroll
    for (int jj = 0; jj < 8; jj++) bv[jj] = bias[tx * 8 + jj];
#pragma unroll
    for (int i = 0; i < 8; i++) {
        int gr = r0 + ty * 8 + i;
        if (gr < NN) {
            float4 o0, o1;
            o0.x = fmaxf(acc[i][0] + bv[0], 0.f);
            o0.y = fmaxf(acc[i][1] + bv[1], 0.f);
            o0.z = fmaxf(acc[i][2] + bv[2], 0.f);
            o0.w = fmaxf(acc[i][3] + bv[3], 0.f);
            o1.x = fmaxf(acc[i][4] + bv[4], 0.f);
            o1.y = fmaxf(acc[i][5] + bv[5], 0.f);
            o1.z = fmaxf(acc[i][6] + bv[6], 0.f);
            o1.w = fmaxf(acc[i][7] + bv[7], 0.f);
            *(float4*)(C + (size_t)gr * 128 + tx * 8)     = o0;
            *(float4*)(C + (size_t)gr * 128 + tx * 8 + 4) = o1;
        }
    }
}

// ---------------- head GEMM: Y = A@W + b, K=128, arbitrary P ----------------
// MODE 0: plain store. MODE 1: BN -> pre to scratch, tanh(pre) to Cmain (P=64).
#define HEAD_SMEM (128 * 128 * 4 + 2 * 8 * AS_STRIDE * 4)

template <int MODE>
__global__ __launch_bounds__(256) void k_head(
    const float* __restrict__ A, const float* __restrict__ W,
    const float* __restrict__ bias, float* __restrict__ Cmain, int P,
    const float* __restrict__ gamma, const float* __restrict__ beta,
    const float* __restrict__ rm, const float* __restrict__ rv,
    float* __restrict__ preout)
{
    extern __shared__ float sm[];
    float* Ws = sm;                 // [128][128]
    float* As = sm + 128 * 128;
    int tid = threadIdx.x;
    int jbase = blockIdx.y * 128;

    for (int i = tid; i < 128 * 128; i += 256) {
        int k = i >> 7, jl = i & 127;
        int jg = jbase + jl;
        Ws[i] = (jg < P) ? W[(size_t)k * P + jg] : 0.f;
    }

    int r0 = blockIdx.x * 128;
    int lrow = tid >> 1;
    int kpart = (tid & 1) * 4;
    int ty = tid >> 4, tx = tid & 15;

    float acc[8][8];
#pragma unroll
    for (int i = 0; i < 8; i++)
#pragma unroll
        for (int jj = 0; jj < 8; jj++) acc[i][jj] = 0.f;

    auto loadA = [&](int kc, int buf) {
        int kg = kc * 8 + kpart;
        int gr = r0 + lrow;
        float4 v = {0.f, 0.f, 0.f, 0.f};
        if (gr < NN) v = *(const float4*)(A + (size_t)gr * 128 + kg);
        float* d2 = As + buf * 8 * AS_STRIDE;
        d2[(kpart + 0) * AS_STRIDE + lrow] = v.x;
        d2[(kpart + 1) * AS_STRIDE + lrow] = v.y;
        d2[(kpart + 2) * AS_STRIDE + lrow] = v.z;
        d2[(kpart + 3) * AS_STRIDE + lrow] = v.w;
    };

    loadA(0, 0);
    __syncthreads();
    for (int kc = 0; kc < 16; kc++) {
        if (kc + 1 < 16) loadA(kc + 1, (kc + 1) & 1);
        const float* Ab = As + (kc & 1) * 8 * AS_STRIDE;
#pragma unroll
        for (int kk = 0; kk < 8; kk++) {
            float a[8], w[8];
            *(float4*)(a)     = *(const float4*)(Ab + kk * AS_STRIDE + ty * 8);
            *(float4*)(a + 4) = *(const float4*)(Ab + kk * AS_STRIDE + ty * 8 + 4);
            const float* wr = Ws + (kc * 8 + kk) * 128 + tx * 8;
            *(float4*)(w)     = *(const float4*)(wr);
            *(float4*)(w + 4) = *(const float4*)(wr + 4);
#pragma unroll
            for (int i = 0; i < 8; i++)
#pragma unroll
                for (int jj = 0; jj < 8; jj++)
                    acc[i][jj] = fmaf(a[i], w[jj], acc[i][jj]);
        }
        __syncthreads();
    }

#pragma unroll
    for (int i = 0; i < 8; i++) {
        int gr = r0 + ty * 8 + i;
        if (gr >= NN) continue;
#pragma unroll
        for (int jj = 0; jj < 8; jj++) {
            int jg = jbase + tx * 8 + jj;
            if (jg >= P) continue;
            float v = acc[i][jj] + bias[jg];
            if (MODE == 0) {
                Cmain[(size_t)gr * P + jg] = v;
            } else {
                float pb = gamma[jg] * (v - rm[jg]) * rsqrtf(rv[jg] + 1e-5f) + beta[jg];
                preout[(size_t)gr * 64 + jg] = pb;
                Cmain[(size_t)gr * 64 + jg] = tanhf(pb);
            }
        }
    }
}

// ---------------- tail: fea_convert = tanh(pre)@wcv+bcv, true_lab = pre@wtl+btl
__global__ __launch_bounds__(256) void k_tail(
    const float* __restrict__ wcv, const float* __restrict__ bcv,
    const float* __restrict__ wtl, const float* __restrict__ btl,
    float* __restrict__ fc, float* __restrict__ tl)
{
    __shared__ float Wc[64 * 100];
    __shared__ float Wt[64];
    __shared__ float Tn[16][66];
    __shared__ float Pr[16][66];
    int tid = threadIdx.x;
    for (int i = tid; i < 6400; i += 256) Wc[i] = wcv[i];
    if (tid < 64) Wt[tid] = wtl[tid];
    int r0 = blockIdx.x * 16;
    for (int i = tid; i < 16 * 64; i += 256) {
        int r = i >> 6, c = i & 63;
        int gr = r0 + r;
        float v = (gr < NN) ? g_pre[(size_t)gr * 64 + c] : 0.f;
        Pr[r][c] = v;
        Tn[r][c] = tanhf(v);
    }
    __syncthreads();
    int ty = tid >> 4, tx = tid & 15;
    int gr = r0 + ty;
    if (gr >= NN) return;
    for (int j = tx; j < 100; j += 16) {
        float s = bcv[j];
#pragma unroll
        for (int k = 0; k < 64; k++) s = fmaf(Tn[ty][k], Wc[k * 100 + j], s);
        fc[(size_t)gr * 100 + j] = s;
    }
    if (tx == 0) {
        float s = btl[0];
#pragma unroll
        for (int k = 0; k < 64; k++) s = fmaf(Pr[ty][k], Wt[k], s);
        tl[gr] = s;
    }
}

// ---------------- launch ----------------------------------------------------
extern "C" void kernel_launch(void* const* d_in, const int* in_sizes, int n_in,
                              void* d_out, int out_size) {
    const float* features = (const float*)d_in[0];
    const int*   edges    = (const int*)d_in[1];
    const float* w1l  = (const float*)d_in[2];
    const float* b1l  = (const float*)d_in[3];
    const float* w1r  = (const float*)d_in[4];
    const float* w2l  = (const float*)d_in[5];
    const float* b2l  = (const float*)d_in[6];
    const float* w2r  = (const float*)d_in[7];
    const float* whd  = (const float*)d_in[8];
    const float* bhd  = (const float*)d_in[9];
    const float* wclas = (const float*)d_in[10];
    const float* bclas = (const float*)d_in[11];
    const float* wconv = (const float*)d_in[12];
    const float* bconv = (const float*)d_in[13];
    const float* gamma = (const float*)d_in[14];
    const float* beta  = (const float*)d_in[15];
    const float* rm    = (const float*)d_in[16];
    const float* rv    = (const float*)d_in[17];
    const float* wtl   = (const float*)d_in[18];
    const float* btl   = (const float*)d_in[19];
    const float* wcv   = (const float*)d_in[20];
    const float* bcv   = (const float*)d_in[21];
    float* out = (float*)d_out;

    float *p_mean, *p_h1, *p_h2, *p_pre;
    cudaGetSymbolAddress((void**)&p_mean, g_mean);
    cudaGetSymbolAddress((void**)&p_h1,   g_h1);
    cudaGetSymbolAddress((void**)&p_h2,   g_h2);
    cudaGetSymbolAddress((void**)&p_pre,  g_pre);

    const int* src = edges;
    const int* dst = edges + NE;

    cudaFuncSetAttribute(k_sage, cudaFuncAttributeMaxDynamicSharedMemorySize, SAGE_SMEM);
    cudaFuncSetAttribute(k_head<0>, cudaFuncAttributeMaxDynamicSharedMemorySize, HEAD_SMEM);
    cudaFuncSetAttribute(k_head<1>, cudaFuncAttributeMaxDynamicSharedMemorySize, HEAD_SMEM);

    // CSR build
    k_zero_cnt<<<(NN + 255) / 256, 256>>>();
    k_count<<<NE / 256, 256>>>(dst);
    k_scan<<<1, 1024>>>();
    k_scatter<<<NE / 256, 256>>>(src, dst);

    // layer 1
    k_agg<<<NN / 8, 256>>>(features, p_mean);
    k_sage<<<391, 256, SAGE_SMEM>>>(p_mean, features, w1l, w1r, b1l, p_h1);
    // layer 2
    k_agg<<<NN / 8, 256>>>(p_h1, p_mean);
    k_sage<<<391, 256, SAGE_SMEM>>>(p_mean, p_h1, w2l, w2r, b2l, p_h2);

    // output layout: [logists(100) | out(64) | fea_lab(300) | fea_convert(100) | true_lab(1)]
    float* o_log = out;
    float* o_out = out + (size_t)NN * 100;
    float* o_fea = out + (size_t)NN * 164;
    float* o_fc  = out + (size_t)NN * 464;
    float* o_tl  = out + (size_t)NN * 564;

    k_head<0><<<dim3(391, 3), 256, HEAD_SMEM>>>(p_h2, whd,   bhd,   o_fea, 300,
                                                nullptr, nullptr, nullptr, nullptr, nullptr);
    k_head<0><<<dim3(391, 1), 256, HEAD_SMEM>>>(p_h2, wclas, bclas, o_log, 100,
                                                nullptr, nullptr, nullptr, nullptr, nullptr);
    k_head<1><<<dim3(391, 1), 256, HEAD_SMEM>>>(p_h2, wconv, bconv, o_out, 64,
                                                gamma, beta, rm, rv, p_pre);
    k_tail<<<NN / 16, 256>>>(wcv, bcv, wtl, btl, o_fc, o_tl);
}

// round 2
// speedup vs baseline: 1.0479x; 1.0479x over previous
#include <cuda_runtime.h>

constexpr int NN = 50000;
constexpr int NE = 800000;

// ---------------- scratch (no allocs allowed; __device__ globals) -----------
__device__ float g_mean[NN * 128];
__device__ float g_h1[NN * 128];
__device__ float g_h2[NN * 128];
__device__ float g_pre[NN * 64];
__device__ int   g_csr[NE];
__device__ int   g_cnt[NN];
__device__ int   g_off[NN + 1];
__device__ int   g_cur[NN];

// packed f32x2 helpers (sm_103a; ptxas will not auto-fuse these)
#define FMA2(d, a, b) \
    asm("fma.rn.f32x2 %0, %1, %2, %0;" : "+l"(d) : "l"(a), "l"(b))
#define PACK_DUP(d, f) \
    asm("mov.b64 %0, {%1, %1};" : "=l"(d) : "r"(__float_as_uint(f)))
#define UNPACK2(lo, hi, v) \
    asm("mov.b64 {%0, %1}, %2;" : "=f"(lo), "=f"(hi) : "l"(v))

// ---------------- CSR build -------------------------------------------------
__global__ void k_zero_cnt() {
    int i = blockIdx.x * blockDim.x + threadIdx.x;
    if (i < NN) g_cnt[i] = 0;
}

__global__ void k_count(const int* __restrict__ dst) {
    int i = blockIdx.x * blockDim.x + threadIdx.x;
    if (i < NE) atomicAdd(&g_cnt[dst[i]], 1);
}

// chunked scan: each thread serially handles 49 counts; one 1024-wide block scan.
__global__ void k_scan() {
    __shared__ int sh[1024];
    const int CH = 49;  // 1024*49 = 50176 >= NN
    int t = threadIdx.x;
    int begin = t * CH;
    int s = 0;
    for (int i = 0; i < CH; i++) {
        int idx = begin + i;
        if (idx < NN) s += g_cnt[idx];
    }
    sh[t] = s;
    __syncthreads();
    for (int ofs = 1; ofs < 1024; ofs <<= 1) {
        int v = (t >= ofs) ? sh[t - ofs] : 0;
        __syncthreads();
        sh[t] += v;
        __syncthreads();
    }
    int run = sh[t] - s;  // exclusive prefix of this chunk
    for (int i = 0; i < CH; i++) {
        int idx = begin + i;
        if (idx < NN) {
            g_off[idx] = run;
            g_cur[idx] = run;
            run += g_cnt[idx];
        }
    }
    if (t == 1023) g_off[NN] = sh[1023];
}

__global__ void k_scatter(const int* __restrict__ src, const int* __restrict__ dst) {
    int i = blockIdx.x * blockDim.x + threadIdx.x;
    if (i < NE) {
        int d = dst[i];
        int pos = atomicAdd(&g_cur[d], 1);
        g_csr[pos] = src[i];
    }
}

// ---------------- aggregation: one warp per node, float4 lanes --------------
__global__ void k_agg(const float* __restrict__ X, float* __restrict__ M) {
    int w = (blockIdx.x * blockDim.x + threadIdx.x) >> 5;
    int lane = threadIdx.x & 31;
    if (w >= NN) return;
    int s = g_off[w], e = g_off[w + 1];
    float4 a0 = {0.f, 0.f, 0.f, 0.f}, a1 = a0, a2 = a0, a3 = a0;
    int j = s;
    for (; j + 4 <= e; j += 4) {
        int i0 = g_csr[j], i1 = g_csr[j + 1], i2 = g_csr[j + 2], i3 = g_csr[j + 3];
        float4 v0 = *(const float4*)(X + (size_t)i0 * 128 + lane * 4);
        float4 v1 = *(const float4*)(X + (size_t)i1 * 128 + lane * 4);
        float4 v2 = *(const float4*)(X + (size_t)i2 * 128 + lane * 4);
        float4 v3 = *(const float4*)(X + (size_t)i3 * 128 + lane * 4);
        a0.x += v0.x; a0.y += v0.y; a0.z += v0.z; a0.w += v0.w;
        a1.x += v1.x; a1.y += v1.y; a1.z += v1.z; a1.w += v1.w;
        a2.x += v2.x; a2.y += v2.y; a2.z += v2.z; a2.w += v2.w;
        a3.x += v3.x; a3.y += v3.y; a3.z += v3.z; a3.w += v3.w;
    }
    for (; j < e; j++) {
        int i0 = g_csr[j];
        float4 v0 = *(const float4*)(X + (size_t)i0 * 128 + lane * 4);
        a0.x += v0.x; a0.y += v0.y; a0.z += v0.z; a0.w += v0.w;
    }
    a0.x += a1.x + a2.x + a3.x;
    a0.y += a1.y + a2.y + a3.y;
    a0.z += a1.z + a2.z + a3.z;
    a0.w += a1.w + a2.w + a3.w;
    int c = e - s; if (c < 1) c = 1;
    float inv = 1.0f / (float)c;
    float4 r; r.x = a0.x * inv; r.y = a0.y * inv; r.z = a0.z * inv; r.w = a0.w * inv;
    *(float4*)(M + (size_t)w * 128 + lane * 4) = r;
}

// ---------------- SAGE GEMM: C = relu(A1@W1 + A2@W2 + b), K=128 each --------
// Block: 128 rows x 128 cols, 256 threads, 8x8 microtile, packed f32x2 FMA.
#define AS_STRIDE 132
#define SAGE_SMEM (256 * 128 * 4 + 2 * 8 * AS_STRIDE * 4)

__global__ __launch_bounds__(256) void k_sage(
    const float* __restrict__ A1, const float* __restrict__ A2,
    const float* __restrict__ W1, const float* __restrict__ W2,
    const float* __restrict__ bias, float* __restrict__ C)
{
    extern __shared__ float sm[];
    float* Ws = sm;                 // [256][128]
    float* As = sm + 256 * 128;     // [2][8][AS_STRIDE]
    int tid = threadIdx.x;

    for (int i = tid; i < 256 * 128 / 4; i += 256) {
        int k = (i * 4) >> 7;
        int jc = (i * 4) & 127;
        const float* p = (k < 128) ? (W1 + (size_t)k * 128 + jc)
                                   : (W2 + (size_t)(k - 128) * 128 + jc);
        ((float4*)Ws)[i] = *(const float4*)p;
    }

    int r0 = blockIdx.x * 128;
    int lrow = tid >> 1;
    int kpart = (tid & 1) * 4;
    int ty = tid >> 4, tx = tid & 15;

    unsigned long long acc[8][4];
#pragma unroll
    for (int i = 0; i < 8; i++)
#pragma unroll
        for (int jj = 0; jj < 4; jj++) acc[i][jj] = 0ULL;

    auto loadA = [&](int kc, int buf) {
        int kg = kc * 8 + kpart;
        const float* srcp = (kg < 128) ? A1 : A2;
        int kk = kg & 127;
        int gr = r0 + lrow;
        float4 v = {0.f, 0.f, 0.f, 0.f};
        if (gr < NN) v = *(const float4*)(srcp + (size_t)gr * 128 + kk);
        float* d2 = As + buf * 8 * AS_STRIDE;
        d2[(kpart + 0) * AS_STRIDE + lrow] = v.x;
        d2[(kpart + 1) * AS_STRIDE + lrow] = v.y;
        d2[(kpart + 2) * AS_STRIDE + lrow] = v.z;
        d2[(kpart + 3) * AS_STRIDE + lrow] = v.w;
    };

    loadA(0, 0);
    __syncthreads();
    for (int kc = 0; kc < 32; kc++) {
        if (kc + 1 < 32) loadA(kc + 1, (kc + 1) & 1);
        const float* Ab = As + (kc & 1) * 8 * AS_STRIDE;
#pragma unroll
        for (int kk = 0; kk < 8; kk++) {
            float a[8];
            *(float4*)(a)     = *(const float4*)(Ab + kk * AS_STRIDE + ty * 8);
            *(float4*)(a + 4) = *(const float4*)(Ab + kk * AS_STRIDE + ty * 8 + 4);
            unsigned long long ad[8];
#pragma unroll
            for (int i = 0; i < 8; i++) PACK_DUP(ad[i], a[i]);
            const float* wr = Ws + (kc * 8 + kk) * 128 + tx * 8;
            ulonglong2 wp0 = *(const ulonglong2*)(wr);
            ulonglong2 wp1 = *(const ulonglong2*)(wr + 4);
            unsigned long long w0 = wp0.x, w1 = wp0.y, w2 = wp1.x, w3 = wp1.y;
#pragma unroll
            for (int i = 0; i < 8; i++) {
                FMA2(acc[i][0], ad[i], w0);
                FMA2(acc[i][1], ad[i], w1);
                FMA2(acc[i][2], ad[i], w2);
                FMA2(acc[i][3], ad[i], w3);
            }
        }
        __syncthreads();
    }

    float bv[8];
#pragma unroll
    for (int jj = 0; jj < 8; jj++) bv[jj] = bias[tx * 8 + jj];
#pragma unroll
    for (int i = 0; i < 8; i++) {
        int gr = r0 + ty * 8 + i;
        if (gr < NN) {
            float f[8];
#pragma unroll
            for (int jp = 0; jp < 4; jp++) UNPACK2(f[2 * jp], f[2 * jp + 1], acc[i][jp]);
            float4 o0, o1;
            o0.x = fmaxf(f[0] + bv[0], 0.f);
            o0.y = fmaxf(f[1] + bv[1], 0.f);
            o0.z = fmaxf(f[2] + bv[2], 0.f);
            o0.w = fmaxf(f[3] + bv[3], 0.f);
            o1.x = fmaxf(f[4] + bv[4], 0.f);
            o1.y = fmaxf(f[5] + bv[5], 0.f);
            o1.z = fmaxf(f[6] + bv[6], 0.f);
            o1.w = fmaxf(f[7] + bv[7], 0.f);
            *(float4*)(C + (size_t)gr * 128 + tx * 8)     = o0;
            *(float4*)(C + (size_t)gr * 128 + tx * 8 + 4) = o1;
        }
    }
}

// ---------------- head GEMM: Y = A@W + b, K=128, arbitrary P ----------------
// MODE 0: plain store. MODE 1: BN -> pre to scratch, tanh(pre) to Cmain (P=64).
#define HEAD_SMEM (128 * 128 * 4 + 2 * 8 * AS_STRIDE * 4)

template <int MODE>
__global__ __launch_bounds__(256) void k_head(
    const float* __restrict__ A, const float* __restrict__ W,
    const float* __restrict__ bias, float* __restrict__ Cmain, int P,
    const float* __restrict__ gamma, const float* __restrict__ beta,
    const float* __restrict__ rm, const float* __restrict__ rv,
    float* __restrict__ preout)
{
    extern __shared__ float sm[];
    float* Ws = sm;                 // [128][128]
    float* As = sm + 128 * 128;
    int tid = threadIdx.x;
    int jbase = blockIdx.y * 128;

    for (int i = tid; i < 128 * 128; i += 256) {
        int k = i >> 7, jl = i & 127;
        int jg = jbase + jl;
        Ws[i] = (jg < P) ? W[(size_t)k * P + jg] : 0.f;
    }

    int r0 = blockIdx.x * 128;
    int lrow = tid >> 1;
    int kpart = (tid & 1) * 4;
    int ty = tid >> 4, tx = tid & 15;

    unsigned long long acc[8][4];
#pragma unroll
    for (int i = 0; i < 8; i++)
#pragma unroll
        for (int jj = 0; jj < 4; jj++) acc[i][jj] = 0ULL;

    auto loadA = [&](int kc, int buf) {
        int kg = kc * 8 + kpart;
        int gr = r0 + lrow;
        float4 v = {0.f, 0.f, 0.f, 0.f};
        if (gr < NN) v = *(const float4*)(A + (size_t)gr * 128 + kg);
        float* d2 = As + buf * 8 * AS_STRIDE;
        d2[(kpart + 0) * AS_STRIDE + lrow] = v.x;
        d2[(kpart + 1) * AS_STRIDE + lrow] = v.y;
        d2[(kpart + 2) * AS_STRIDE + lrow] = v.z;
        d2[(kpart + 3) * AS_STRIDE + lrow] = v.w;
    };

    loadA(0, 0);
    __syncthreads();
    for (int kc = 0; kc < 16; kc++) {
        if (kc + 1 < 16) loadA(kc + 1, (kc + 1) & 1);
        const float* Ab = As + (kc & 1) * 8 * AS_STRIDE;
#pragma unroll
        for (int kk = 0; kk < 8; kk++) {
            float a[8];
            *(float4*)(a)     = *(const float4*)(Ab + kk * AS_STRIDE + ty * 8);
            *(float4*)(a + 4) = *(const float4*)(Ab + kk * AS_STRIDE + ty * 8 + 4);
            unsigned long long ad[8];
#pragma unroll
            for (int i = 0; i < 8; i++) PACK_DUP(ad[i], a[i]);
            const float* wr = Ws + (kc * 8 + kk) * 128 + tx * 8;
            ulonglong2 wp0 = *(const ulonglong2*)(wr);
            ulonglong2 wp1 = *(const ulonglong2*)(wr + 4);
            unsigned long long w0 = wp0.x, w1 = wp0.y, w2 = wp1.x, w3 = wp1.y;
#pragma unroll
            for (int i = 0; i < 8; i++) {
                FMA2(acc[i][0], ad[i], w0);
                FMA2(acc[i][1], ad[i], w1);
                FMA2(acc[i][2], ad[i], w2);
                FMA2(acc[i][3], ad[i], w3);
            }
        }
        __syncthreads();
    }

#pragma unroll
    for (int i = 0; i < 8; i++) {
        int gr = r0 + ty * 8 + i;
        if (gr >= NN) continue;
        float f[8];
#pragma unroll
        for (int jp = 0; jp < 4; jp++) UNPACK2(f[2 * jp], f[2 * jp + 1], acc[i][jp]);
#pragma unroll
        for (int jj = 0; jj < 8; jj++) {
            int jg = jbase + tx * 8 + jj;
            if (jg >= P) continue;
            float v = f[jj] + bias[jg];
            if (MODE == 0) {
                Cmain[(size_t)gr * P + jg] = v;
            } else {
                float pb = gamma[jg] * (v - rm[jg]) * rsqrtf(rv[jg] + 1e-5f) + beta[jg];
                preout[(size_t)gr * 64 + jg] = pb;
                Cmain[(size_t)gr * 64 + jg] = tanhf(pb);
            }
        }
    }
}

// ---------------- tail: fea_convert = tanh(pre)@wcv+bcv, true_lab = pre@wtl+btl
__global__ __launch_bounds__(256) void k_tail(
    const float* __restrict__ wcv, const float* __restrict__ bcv,
    const float* __restrict__ wtl, const float* __restrict__ btl,
    float* __restrict__ fc, float* __restrict__ tl)
{
    __shared__ float Wc[64 * 100];
    __shared__ float Wt[64];
    __shared__ float Tn[16][66];
    __shared__ float Pr[16][66];
    int tid = threadIdx.x;
    for (int i = tid; i < 6400; i += 256) Wc[i] = wcv[i];
    if (tid < 64) Wt[tid] = wtl[tid];
    int r0 = blockIdx.x * 16;
    for (int i = tid; i < 16 * 64; i += 256) {
        int r = i >> 6, c = i & 63;
        int gr = r0 + r;
        float v = (gr < NN) ? g_pre[(size_t)gr * 64 + c] : 0.f;
        Pr[r][c] = v;
        Tn[r][c] = tanhf(v);
    }
    __syncthreads();
    int ty = tid >> 4, tx = tid & 15;
    int gr = r0 + ty;
    if (gr >= NN) return;
    for (int j = tx; j < 100; j += 16) {
        float s = bcv[j];
#pragma unroll
        for (int k = 0; k < 64; k++) s = fmaf(Tn[ty][k], Wc[k * 100 + j], s);
        fc[(size_t)gr * 100 + j] = s;
    }
    if (tx == 0) {
        float s = btl[0];
#pragma unroll
        for (int k = 0; k < 64; k++) s = fmaf(Pr[ty][k], Wt[k], s);
        tl[gr] = s;
    }
}

// ---------------- launch ----------------------------------------------------
extern "C" void kernel_launch(void* const* d_in, const int* in_sizes, int n_in,
                              void* d_out, int out_size) {
    const float* features = (const float*)d_in[0];
    const int*   edges    = (const int*)d_in[1];
    const float* w1l  = (const float*)d_in[2];
    const float* b1l  = (const float*)d_in[3];
    const float* w1r  = (const float*)d_in[4];
    const float* w2l  = (const float*)d_in[5];
    const float* b2l  = (const float*)d_in[6];
    const float* w2r  = (const float*)d_in[7];
    const float* whd  = (const float*)d_in[8];
    const float* bhd  = (const float*)d_in[9];
    const float* wclas = (const float*)d_in[10];
    const float* bclas = (const float*)d_in[11];
    const float* wconv = (const float*)d_in[12];
    const float* bconv = (const float*)d_in[13];
    const float* gamma = (const float*)d_in[14];
    const float* beta  = (const float*)d_in[15];
    const float* rm    = (const float*)d_in[16];
    const float* rv    = (const float*)d_in[17];
    const float* wtl   = (const float*)d_in[18];
    const float* btl   = (const float*)d_in[19];
    const float* wcv   = (const float*)d_in[20];
    const float* bcv   = (const float*)d_in[21];
    float* out = (float*)d_out;

    float *p_mean, *p_h1, *p_h2, *p_pre;
    cudaGetSymbolAddress((void**)&p_mean, g_mean);
    cudaGetSymbolAddress((void**)&p_h1,   g_h1);
    cudaGetSymbolAddress((void**)&p_h2,   g_h2);
    cudaGetSymbolAddress((void**)&p_pre,  g_pre);

    const int* src = edges;
    const int* dst = edges + NE;

    cudaFuncSetAttribute(k_sage, cudaFuncAttributeMaxDynamicSharedMemorySize, SAGE_SMEM);
    cudaFuncSetAttribute(k_head<0>, cudaFuncAttributeMaxDynamicSharedMemorySize, HEAD_SMEM);
    cudaFuncSetAttribute(k_head<1>, cudaFuncAttributeMaxDynamicSharedMemorySize, HEAD_SMEM);

    // CSR build
    k_zero_cnt<<<(NN + 255) / 256, 256>>>();
    k_count<<<NE / 256, 256>>>(dst);
    k_scan<<<1, 1024>>>();
    k_scatter<<<NE / 256, 256>>>(src, dst);

    // layer 1
    k_agg<<<NN / 8, 256>>>(features, p_mean);
    k_sage<<<391, 256, SAGE_SMEM>>>(p_mean, features, w1l, w1r, b1l, p_h1);
    // layer 2
    k_agg<<<NN / 8, 256>>>(p_h1, p_mean);
    k_sage<<<391, 256, SAGE_SMEM>>>(p_mean, p_h1, w2l, w2r, b2l, p_h2);

    // output layout: [logists(100) | out(64) | fea_lab(300) | fea_convert(100) | true_lab(1)]
    float* o_log = out;
    float* o_out = out + (size_t)NN * 100;
    float* o_fea = out + (size_t)NN * 164;
    float* o_fc  = out + (size_t)NN * 464;
    float* o_tl  = out + (size_t)NN * 564;

    k_head<0><<<dim3(391, 3), 256, HEAD_SMEM>>>(p_h2, whd,   bhd,   o_fea, 300,
                                                nullptr, nullptr, nullptr, nullptr, nullptr);
    k_head<0><<<dim3(391, 1), 256, HEAD_SMEM>>>(p_h2, wclas, bclas, o_log, 100,
                                                nullptr, nullptr, nullptr, nullptr, nullptr);
    k_head<1><<<dim3(391, 1), 256, HEAD_SMEM>>>(p_h2, wconv, bconv, o_out, 64,
                                                gamma, beta, rm, rv, p_pre);
    k_tail<<<NN / 16, 256>>>(wcv, bcv, wtl, btl, o_fc, o_tl);
}

// round 6
// speedup vs baseline: 1.1662x; 1.1129x over previous
#include <cuda_runtime.h>

constexpr int NN = 50000;
constexpr int NE = 800000;

// ---------------- scratch (no allocs allowed; __device__ globals) -----------
__device__ float g_mean[NN * 128];
__device__ float g_h1[NN * 128];
__device__ float g_h2[NN * 128];
__device__ float g_pre[NN * 64];
__device__ int   g_csr[NE];
__device__ int   g_cnt[NN];
__device__ int   g_off[NN + 1];
__device__ int   g_cur[NN];

// packed f32x2 helpers (sm_103a; ptxas will not auto-fuse these)
#define FMA2(d, a, b) \
    asm("fma.rn.f32x2 %0, %1, %2, %0;" : "+l"(d) : "l"(a), "l"(b))
#define PACK_DUP(d, f) \
    asm("mov.b64 %0, {%1, %1};" : "=l"(d) : "r"(__float_as_uint(f)))
#define UNPACK2(lo, hi, v) \
    asm("mov.b64 {%0, %1}, %2;" : "=f"(lo), "=f"(hi) : "l"(v))

// ---------------- CSR build -------------------------------------------------
__global__ void k_zero_cnt() {
    int i = blockIdx.x * blockDim.x + threadIdx.x;
    if (i < NN) g_cnt[i] = 0;
}

__global__ void k_count(const int* __restrict__ dst) {
    int i = blockIdx.x * blockDim.x + threadIdx.x;
    if (i < NE) atomicAdd(&g_cnt[dst[i]], 1);
}

// chunked scan: each thread serially handles 49 counts; one 1024-wide block scan.
__global__ void k_scan() {
    __shared__ int sh[1024];
    const int CH = 49;  // 1024*49 = 50176 >= NN
    int t = threadIdx.x;
    int begin = t * CH;
    int s = 0;
    for (int i = 0; i < CH; i++) {
        int idx = begin + i;
        if (idx < NN) s += g_cnt[idx];
    }
    sh[t] = s;
    __syncthreads();
    for (int ofs = 1; ofs < 1024; ofs <<= 1) {
        int v = (t >= ofs) ? sh[t - ofs] : 0;
        __syncthreads();
        sh[t] += v;
        __syncthreads();
    }
    int run = sh[t] - s;  // exclusive prefix of this chunk
    for (int i = 0; i < CH; i++) {
        int idx = begin + i;
        if (idx < NN) {
            g_off[idx] = run;
            g_cur[idx] = run;
            run += g_cnt[idx];
        }
    }
    if (t == 1023) g_off[NN] = sh[1023];
}

__global__ void k_scatter(const int* __restrict__ src, const int* __restrict__ dst) {
    int i = blockIdx.x * blockDim.x + threadIdx.x;
    if (i < NE) {
        int d = dst[i];
        int pos = atomicAdd(&g_cur[d], 1);
        g_csr[pos] = src[i];
    }
}

// ---------------- aggregation: one warp per node, float4 lanes --------------
__global__ void k_agg(const float* __restrict__ X, float* __restrict__ M) {
    int w = (blockIdx.x * blockDim.x + threadIdx.x) >> 5;
    int lane = threadIdx.x & 31;
    if (w >= NN) return;
    int s = g_off[w], e = g_off[w + 1];
    float4 a0 = {0.f, 0.f, 0.f, 0.f}, a1 = a0, a2 = a0, a3 = a0;
    int j = s;
    for (; j + 4 <= e; j += 4) {
        int i0 = g_csr[j], i1 = g_csr[j + 1], i2 = g_csr[j + 2], i3 = g_csr[j + 3];
        float4 v0 = *(const float4*)(X + (size_t)i0 * 128 + lane * 4);
        float4 v1 = *(const float4*)(X + (size_t)i1 * 128 + lane * 4);
        float4 v2 = *(const float4*)(X + (size_t)i2 * 128 + lane * 4);
        float4 v3 = *(const float4*)(X + (size_t)i3 * 128 + lane * 4);
        a0.x += v0.x; a0.y += v0.y; a0.z += v0.z; a0.w += v0.w;
        a1.x += v1.x; a1.y += v1.y; a1.z += v1.z; a1.w += v1.w;
        a2.x += v2.x; a2.y += v2.y; a2.z += v2.z; a2.w += v2.w;
        a3.x += v3.x; a3.y += v3.y; a3.z += v3.z; a3.w += v3.w;
    }
    for (; j < e; j++) {
        int i0 = g_csr[j];
        float4 v0 = *(const float4*)(X + (size_t)i0 * 128 + lane * 4);
        a0.x += v0.x; a0.y += v0.y; a0.z += v0.z; a0.w += v0.w;
    }
    a0.x += a1.x + a2.x + a3.x;
    a0.y += a1.y + a2.y + a3.y;
    a0.z += a1.z + a2.z + a3.z;
    a0.w += a1.w + a2.w + a3.w;
    int c = e - s; if (c < 1) c = 1;
    float inv = 1.0f / (float)c;
    float4 r; r.x = a0.x * inv; r.y = a0.y * inv; r.z = a0.z * inv; r.w = a0.w * inv;
    *(float4*)(M + (size_t)w * 128 + lane * 4) = r;
}

// ---------------- SAGE GEMM: C = relu([A1|A2]@[W1;W2] + b) ------------------
// 128x128 tile, 256 threads, 8x8 microtile, FFMA2, streamed A+W (16.6KB smem).
#define AS_STRIDE 132

__global__ __launch_bounds__(256) void k_sage(
    const float* __restrict__ A1, const float* __restrict__ A2,
    const float* __restrict__ W1, const float* __restrict__ W2,
    const float* __restrict__ bias, float* __restrict__ C)
{
    __shared__ float Ws[2][8 * 128];
    __shared__ float As[2][8 * AS_STRIDE];
    int tid = threadIdx.x;
    int r0 = blockIdx.x * 128;
    int lrow = tid >> 1;
    int kpart = (tid & 1) * 4;
    int ty = tid >> 4, tx = tid & 15;
    int wrow = tid >> 5, wcol = (tid & 31) * 4;
    int gr_l = r0 + lrow;

    unsigned long long acc[8][4];
#pragma unroll
    for (int i = 0; i < 8; i++)
#pragma unroll
        for (int jj = 0; jj < 4; jj++) acc[i][jj] = 0ULL;

    float4 av, wv;
    auto ldg = [&](int kc) {
        int kg = kc * 8 + kpart;
        const float* sp = (kg < 128) ? A1 : A2;
        int kk = kg & 127;
        av = make_float4(0.f, 0.f, 0.f, 0.f);
        if (gr_l < NN) av = *(const float4*)(sp + (size_t)gr_l * 128 + kk);
        int row = kc * 8 + wrow;
        const float* wp = (row < 128) ? (W1 + (size_t)row * 128)
                                      : (W2 + (size_t)(row - 128) * 128);
        wv = *(const float4*)(wp + wcol);
    };
    auto sts = [&](int buf) {
        float* d = As[buf];
        d[(kpart + 0) * AS_STRIDE + lrow] = av.x;
        d[(kpart + 1) * AS_STRIDE + lrow] = av.y;
        d[(kpart + 2) * AS_STRIDE + lrow] = av.z;
        d[(kpart + 3) * AS_STRIDE + lrow] = av.w;
        *(float4*)(&Ws[buf][wrow * 128 + wcol]) = wv;
    };

    ldg(0);
    sts(0);
    __syncthreads();
    for (int kc = 0; kc < 32; kc++) {
        if (kc < 31) ldg(kc + 1);
        const float* Ab = As[kc & 1];
        const float* Wb = Ws[kc & 1];
#pragma unroll
        for (int kk = 0; kk < 8; kk++) {
            float a[8];
            *(float4*)(a)     = *(const float4*)(Ab + kk * AS_STRIDE + ty * 8);
            *(float4*)(a + 4) = *(const float4*)(Ab + kk * AS_STRIDE + ty * 8 + 4);
            unsigned long long ad[8];
#pragma unroll
            for (int i = 0; i < 8; i++) PACK_DUP(ad[i], a[i]);
            const float* wr = Wb + kk * 128 + tx * 8;
            ulonglong2 wp0 = *(const ulonglong2*)(wr);
            ulonglong2 wp1 = *(const ulonglong2*)(wr + 4);
            unsigned long long w0 = wp0.x, w1 = wp0.y, w2 = wp1.x, w3 = wp1.y;
#pragma unroll
            for (int i = 0; i < 8; i++) {
                FMA2(acc[i][0], ad[i], w0);
                FMA2(acc[i][1], ad[i], w1);
                FMA2(acc[i][2], ad[i], w2);
                FMA2(acc[i][3], ad[i], w3);
            }
        }
        if (kc < 31) sts((kc + 1) & 1);
        __syncthreads();
    }

    float bv[8];
#pragma unroll
    for (int jj = 0; jj < 8; jj++) bv[jj] = bias[tx * 8 + jj];
#pragma unroll
    for (int i = 0; i < 8; i++) {
        int gr = r0 + ty * 8 + i;
        if (gr < NN) {
            float f[8];
#pragma unroll
            for (int jp = 0; jp < 4; jp++) UNPACK2(f[2 * jp], f[2 * jp + 1], acc[i][jp]);
            float4 o0, o1;
            o0.x = fmaxf(f[0] + bv[0], 0.f);
            o0.y = fmaxf(f[1] + bv[1], 0.f);
            o0.z = fmaxf(f[2] + bv[2], 0.f);
            o0.w = fmaxf(f[3] + bv[3], 0.f);
            o1.x = fmaxf(f[4] + bv[4], 0.f);
            o1.y = fmaxf(f[5] + bv[5], 0.f);
            o1.z = fmaxf(f[6] + bv[6], 0.f);
            o1.w = fmaxf(f[7] + bv[7], 0.f);
            *(float4*)(C + (size_t)gr * 128 + tx * 8)     = o0;
            *(float4*)(C + (size_t)gr * 128 + tx * 8 + 4) = o1;
        }
    }
}

// ---------------- fused heads: gridDim.y = 5 --------------------------------
// y=0..2: fea_lab (P=300, jbase=y*128); y=3: logists (P=100); y=4: conv+BN+tanh.
__global__ __launch_bounds__(256) void k_heads(
    const float* __restrict__ A,
    const float* __restrict__ whd,   const float* __restrict__ bhd,
    const float* __restrict__ wclas, const float* __restrict__ bclas,
    const float* __restrict__ wconv, const float* __restrict__ bconv,
    const float* __restrict__ gamma, const float* __restrict__ beta,
    const float* __restrict__ rm,    const float* __restrict__ rv,
    float* __restrict__ o_fea, float* __restrict__ o_log,
    float* __restrict__ o_out, float* __restrict__ pre)
{
    __shared__ float Ws[2][8 * 128];
    __shared__ float As[2][8 * AS_STRIDE];
    int tid = threadIdx.x;
    int by = blockIdx.y;

    const float* W; const float* bias; float* Out; int P; int jbase; int mode = 0;
    if (by < 3)       { W = whd;   bias = bhd;   Out = o_fea; P = 300; jbase = by * 128; }
    else if (by == 3) { W = wclas; bias = bclas; Out = o_log; P = 100; jbase = 0; }
    else              { W = wconv; bias = bconv; Out = o_out; P = 64;  jbase = 0; mode = 1; }

    int r0 = blockIdx.x * 128;
    int lrow = tid >> 1;
    int kpart = (tid & 1) * 4;
    int ty = tid >> 4, tx = tid & 15;
    int wrow = tid >> 5, wcol = (tid & 31) * 4;
    int gr_l = r0 + lrow;

    unsigned long long acc[8][4];
#pragma unroll
    for (int i = 0; i < 8; i++)
#pragma unroll
        for (int jj = 0; jj < 4; jj++) acc[i][jj] = 0ULL;

    float4 av;
    float wreg[4];
    auto ldg = [&](int kc) {
        int kg = kc * 8 + kpart;
        av = make_float4(0.f, 0.f, 0.f, 0.f);
        if (gr_l < NN) av = *(const float4*)(A + (size_t)gr_l * 128 + kg);
        const float* wp = W + (size_t)(kc * 8 + wrow) * P;
#pragma unroll
        for (int e = 0; e < 4; e++) {
            int jg = jbase + wcol + e;
            wreg[e] = (jg < P) ? wp[jg] : 0.f;
        }
    };
    auto sts = [&](int buf) {
        float* d = As[buf];
        d[(kpart + 0) * AS_STRIDE + lrow] = av.x;
        d[(kpart + 1) * AS_STRIDE + lrow] = av.y;
        d[(kpart + 2) * AS_STRIDE + lrow] = av.z;
        d[(kpart + 3) * AS_STRIDE + lrow] = av.w;
        float* wd = &Ws[buf][wrow * 128 + wcol];
        wd[0] = wreg[0]; wd[1] = wreg[1]; wd[2] = wreg[2]; wd[3] = wreg[3];
    };

    ldg(0);
    sts(0);
    __syncthreads();
    for (int kc = 0; kc < 16; kc++) {
        if (kc < 15) ldg(kc + 1);
        const float* Ab = As[kc & 1];
        const float* Wb = Ws[kc & 1];
#pragma unroll
        for (int kk = 0; kk < 8; kk++) {
            float a[8];
            *(float4*)(a)     = *(const float4*)(Ab + kk * AS_STRIDE + ty * 8);
            *(float4*)(a + 4) = *(const float4*)(Ab + kk * AS_STRIDE + ty * 8 + 4);
            unsigned long long ad[8];
#pragma unroll
            for (int i = 0; i < 8; i++) PACK_DUP(ad[i], a[i]);
            const float* wr = Wb + kk * 128 + tx * 8;
            ulonglong2 wp0 = *(const ulonglong2*)(wr);
            ulonglong2 wp1 = *(const ulonglong2*)(wr + 4);
            unsigned long long w0 = wp0.x, w1 = wp0.y, w2 = wp1.x, w3 = wp1.y;
#pragma unroll
            for (int i = 0; i < 8; i++) {
                FMA2(acc[i][0], ad[i], w0);
                FMA2(acc[i][1], ad[i], w1);
                FMA2(acc[i][2], ad[i], w2);
                FMA2(acc[i][3], ad[i], w3);
            }
        }
        if (kc < 15) sts((kc + 1) & 1);
        __syncthreads();
    }

#pragma unroll
    for (int i = 0; i < 8; i++) {
        int gr = r0 + ty * 8 + i;
        if (gr >= NN) continue;
        float f[8];
#pragma unroll
        for (int jp = 0; jp < 4; jp++) UNPACK2(f[2 * jp], f[2 * jp + 1], acc[i][jp]);
#pragma unroll
        for (int jj = 0; jj < 8; jj++) {
            int jg = jbase + tx * 8 + jj;
            if (jg >= P) continue;
            float v = f[jj] + bias[jg];
            if (mode == 0) {
                Out[(size_t)gr * P + jg] = v;
            } else {
                float pb = gamma[jg] * (v - rm[jg]) * rsqrtf(rv[jg] + 1e-5f) + beta[jg];
                pre[(size_t)gr * 64 + jg] = pb;
                Out[(size_t)gr * 64 + jg] = tanhf(pb);
            }
        }
    }
}

// ---------------- tail: fea_convert = tanh(pre)@wcv+bcv, true_lab = pre@wtl+btl
__global__ __launch_bounds__(256) void k_tail(
    const float* __restrict__ wcv, const float* __restrict__ bcv,
    const float* __restrict__ wtl, const float* __restrict__ btl,
    float* __restrict__ fc, float* __restrict__ tl)
{
    __shared__ float Wc[64 * 100];
    __shared__ float Wt[64];
    __shared__ float Tn[16][66];
    __shared__ float Pr[16][66];
    int tid = threadIdx.x;
    for (int i = tid; i < 6400; i += 256) Wc[i] = wcv[i];
    if (tid < 64) Wt[tid] = wtl[tid];
    int r0 = blockIdx.x * 16;
    for (int i = tid; i < 16 * 64; i += 256) {
        int r = i >> 6, c = i & 63;
        int gr = r0 + r;
        float v = (gr < NN) ? g_pre[(size_t)gr * 64 + c] : 0.f;
        Pr[r][c] = v;
        Tn[r][c] = tanhf(v);
    }
    __syncthreads();
    int ty = tid >> 4, tx = tid & 15;
    int gr = r0 + ty;
    if (gr >= NN) return;
    for (int j = tx; j < 100; j += 16) {
        float s = bcv[j];
#pragma unroll
        for (int k = 0; k < 64; k++) s = fmaf(Tn[ty][k], Wc[k * 100 + j], s);
        fc[(size_t)gr * 100 + j] = s;
    }
    if (tx == 0) {
        float s = btl[0];
#pragma unroll
        for (int k = 0; k < 64; k++) s = fmaf(Pr[ty][k], Wt[k], s);
        tl[gr] = s;
    }
}

// ---------------- launch ----------------------------------------------------
extern "C" void kernel_launch(void* const* d_in, const int* in_sizes, int n_in,
                              void* d_out, int out_size) {
    const float* features = (const float*)d_in[0];
    const int*   edges    = (const int*)d_in[1];
    const float* w1l  = (const float*)d_in[2];
    const float* b1l  = (const float*)d_in[3];
    const float* w1r  = (const float*)d_in[4];
    const float* w2l  = (const float*)d_in[5];
    const float* b2l  = (const float*)d_in[6];
    const float* w2r  = (const float*)d_in[7];
    const float* whd  = (const float*)d_in[8];
    const float* bhd  = (const float*)d_in[9];
    const float* wclas = (const float*)d_in[10];
    const float* bclas = (const float*)d_in[11];
    const float* wconv = (const float*)d_in[12];
    const float* bconv = (const float*)d_in[13];
    const float* gamma = (const float*)d_in[14];
    const float* beta  = (const float*)d_in[15];
    const float* rm    = (const float*)d_in[16];
    const float* rv    = (const float*)d_in[17];
    const float* wtl   = (const float*)d_in[18];
    const float* btl   = (const float*)d_in[19];
    const float* wcv   = (const float*)d_in[20];
    const float* bcv   = (const float*)d_in[21];
    float* out = (float*)d_out;

    float *p_mean, *p_h1, *p_h2, *p_pre;
    cudaGetSymbolAddress((void**)&p_mean, g_mean);
    cudaGetSymbolAddress((void**)&p_h1,   g_h1);
    cudaGetSymbolAddress((void**)&p_h2,   g_h2);
    cudaGetSymbolAddress((void**)&p_pre,  g_pre);

    const int* src = edges;
    const int* dst = edges + NE;

    // CSR build
    k_zero_cnt<<<(NN + 255) / 256, 256>>>();
    k_count<<<NE / 256, 256>>>(dst);
    k_scan<<<1, 1024>>>();
    k_scatter<<<NE / 256, 256>>>(src, dst);

    // layer 1
    k_agg<<<NN / 8, 256>>>(features, p_mean);
    k_sage<<<391, 256>>>(p_mean, features, w1l, w1r, b1l, p_h1);
    // layer 2
    k_agg<<<NN / 8, 256>>>(p_h1, p_mean);
    k_sage<<<391, 256>>>(p_mean, p_h1, w2l, w2r, b2l, p_h2);

    // output layout: [logists(100) | out(64) | fea_lab(300) | fea_convert(100) | true_lab(1)]
    float* o_log = out;
    float* o_out = out + (size_t)NN * 100;
    float* o_fea = out + (size_t)NN * 164;
    float* o_fc  = out + (size_t)NN * 464;
    float* o_tl  = out + (size_t)NN * 564;

    k_heads<<<dim3(391, 5), 256>>>(p_h2, whd, bhd, wclas, bclas, wconv, bconv,
                                   gamma, beta, rm, rv,
                                   o_fea, o_log, o_out, p_pre);
    k_tail<<<NN / 16, 256>>>(wcv, bcv, wtl, btl, o_fc, o_tl);
}